// round 1
// baseline (speedup 1.0000x reference)
#include <cuda_runtime.h>

#define FULL 0xffffffffu

struct C { float x, y; };

__device__ __forceinline__ C cmul(C a, C b) {
    C r; r.x = a.x*b.x - a.y*b.y; r.y = a.x*b.y + a.y*b.x; return r;
}
// acc + a*b
__device__ __forceinline__ C cmadd(C a, C b, C acc) {
    C r;
    r.x = fmaf(a.x, b.x, fmaf(-a.y, b.y, acc.x));
    r.y = fmaf(a.x, b.y, fmaf( a.y, b.x, acc.y));
    return r;
}

__global__ void __launch_bounds__(256)
qsim_kernel(const float* __restrict__ x,
            const float* __restrict__ weights,
            const float* __restrict__ post_W,
            const float* __restrict__ post_b,
            const float* __restrict__ readout,
            const float* __restrict__ bias,
            float* __restrict__ out,
            int batch)
{
    const int lane = threadIdx.x & 31;
    const int samp = (int)((blockIdx.x * blockDim.x + threadIdx.x) >> 5);
    if (samp >= batch) return;

    // Per-sample encoding angles: only x0, x1 exist.
    const float x0 = x[2*samp + 0];
    const float x1 = x[2*samp + 1];
    float sx0, cx0, sx1, cx1;
    __sincosf(0.5f * x0, &sx0, &cx0);
    __sincosf(0.5f * x1, &sx1, &cx1);

    // State: amplitude index i = r*32 + lane; bit(9-w) selects wire w.
    C amp[32];
#pragma unroll
    for (int r = 0; r < 32; r++) { amp[r].x = 0.f; amp[r].y = 0.f; }
    if (lane == 0) amp[0].x = 1.0f;

#pragma unroll 1
    for (int layer = 0; layer < 6; layer++) {
        const float* wl = weights + layer * 30;

        // Fused per-wire gate: M = Rot(phi,theta,omega) * RY(x_{(w+1)%2}) * RX(x_{w%2})
#pragma unroll
        for (int w = 0; w < 10; w++) {
            const float phi = wl[3*w + 0];
            const float th  = wl[3*w + 1];
            const float om  = wl[3*w + 2];
            float st, ct, sa, ca, sb, cb;
            __sincosf(0.5f * th,        &st, &ct);
            __sincosf(0.5f * (phi+om),  &sa, &ca);
            __sincosf(0.5f * (phi-om),  &sb, &cb);
            // Rot entries
            C u00 = { ca*ct, -sa*ct };
            C u01 = { -cb*st, -sb*st };
            C u10 = { cb*st, -sb*st };
            C u11 = { ca*ct,  sa*ct };
            // RX uses x[w%2], RY uses x[(w+1)%2]
            const float c1 = (w & 1) ? cx1 : cx0;  // RX
            const float s1 = (w & 1) ? sx1 : sx0;
            const float c2 = (w & 1) ? cx0 : cx1;  // RY
            const float s2 = (w & 1) ? sx0 : sx1;
            // G = RY @ RX
            C g00 = {  c2*c1,  s2*s1 };
            C g01 = { -s2*c1, -c2*s1 };
            C g10 = {  s2*c1, -c2*s1 };
            C g11 = {  c2*c1, -s2*s1 };
            // M = Rot @ G
            C m00 = cmadd(u00, g00, cmul(u01, g10));
            C m01 = cmadd(u00, g01, cmul(u01, g11));
            C m10 = cmadd(u10, g00, cmul(u11, g10));
            C m11 = cmadd(u10, g01, cmul(u11, g11));

            const int b = 9 - w;  // bit position
            if (b >= 5) {
                // register-bit gate
                const int s = 1 << (b - 5);
#pragma unroll
                for (int r = 0; r < 32; r++) {
                    if (r & s) continue;
                    C a = amp[r], d = amp[r | s];
                    amp[r]     = cmadd(m01, d, cmul(m00, a));
                    amp[r | s] = cmadd(m11, d, cmul(m10, a));
                }
            } else {
                // lane-bit gate: exchange partner via shuffle
                const int m = 1 << b;
                const bool hi = (lane & m) != 0;
                C cm = hi ? m11 : m00;  // coefficient for own amplitude
                C co = hi ? m10 : m01;  // coefficient for partner amplitude
#pragma unroll
                for (int r = 0; r < 32; r++) {
                    C o;
                    o.x = __shfl_xor_sync(FULL, amp[r].x, m);
                    o.y = __shfl_xor_sync(FULL, amp[r].y, m);
                    amp[r] = cmadd(co, o, cmul(cm, amp[r]));
                }
            }
        }

        // CNOT ring: ctrl=w (bit 9-w), tgt=(w+1)%10 (bit 8-w, or 9 for w=9)
#pragma unroll
        for (int w = 0; w < 10; w++) {
            const int cb = 9 - w;
            const int tb = (w < 9) ? (8 - w) : 9;
            if (cb >= 5 && tb >= 5) {
                const int cs = 1 << (cb - 5), ts = 1 << (tb - 5);
#pragma unroll
                for (int r = 0; r < 32; r++) {
                    if ((r & cs) && !(r & ts)) {
                        C t = amp[r]; amp[r] = amp[r | ts]; amp[r | ts] = t;
                    }
                }
            } else if (cb < 5 && tb >= 5) {
                const int ts = 1 << (tb - 5);
                const bool c = (lane & (1 << cb)) != 0;
#pragma unroll
                for (int r = 0; r < 32; r++) {
                    if (r & ts) continue;
                    C a = amp[r], d = amp[r | ts];
                    amp[r].x      = c ? d.x : a.x;
                    amp[r].y      = c ? d.y : a.y;
                    amp[r | ts].x = c ? a.x : d.x;
                    amp[r | ts].y = c ? a.y : d.y;
                }
            } else if (cb >= 5 && tb < 5) {
                const int cs = 1 << (cb - 5), m = 1 << tb;
#pragma unroll
                for (int r = 0; r < 32; r++) {
                    if (!(r & cs)) continue;
                    amp[r].x = __shfl_xor_sync(FULL, amp[r].x, m);
                    amp[r].y = __shfl_xor_sync(FULL, amp[r].y, m);
                }
            } else {
                const int m = 1 << tb;
                const bool c = (lane & (1 << cb)) != 0;
#pragma unroll
                for (int r = 0; r < 32; r++) {
                    float ox = __shfl_xor_sync(FULL, amp[r].x, m);
                    float oy = __shfl_xor_sync(FULL, amp[r].y, m);
                    amp[r].x = c ? ox : amp[r].x;
                    amp[r].y = c ? oy : amp[r].y;
                }
            }
        }
    }

    // Readout: out = readout * (sum_i |amp_i|^2 * coef_i + post_b) + bias
    // coef_i = sum_w post_W[w] * (+1 if bit(9-w)=0 else -1)
    float pw[10];
#pragma unroll
    for (int w = 0; w < 10; w++) pw[w] = post_W[w];

    float laneCoef = 0.f;
#pragma unroll
    for (int w = 5; w < 10; w++) {
        laneCoef += ((lane >> (9 - w)) & 1) ? -pw[w] : pw[w];
    }

    float acc = 0.f;
#pragma unroll
    for (int r = 0; r < 32; r++) {
        float coef = laneCoef;
#pragma unroll
        for (int w = 0; w < 5; w++) {
            coef += ((r >> (4 - w)) & 1) ? -pw[w] : pw[w];
        }
        float prob = fmaf(amp[r].x, amp[r].x, amp[r].y * amp[r].y);
        acc = fmaf(prob, coef, acc);
    }

#pragma unroll
    for (int off = 16; off; off >>= 1)
        acc += __shfl_xor_sync(FULL, acc, off);

    if (lane == 0) {
        out[samp] = readout[0] * (acc + post_b[0]) + bias[0];
    }
}

extern "C" void kernel_launch(void* const* d_in, const int* in_sizes, int n_in,
                              void* d_out, int out_size)
{
    const float* x       = (const float*)d_in[0];
    const float* weights = (const float*)d_in[1];
    const float* post_W  = (const float*)d_in[2];
    const float* post_b  = (const float*)d_in[3];
    const float* readout = (const float*)d_in[4];
    const float* bias    = (const float*)d_in[5];
    float* out = (float*)d_out;

    const int batch = in_sizes[0] / 2;          // x is [B, 2]
    const int threads = 256;                    // 8 warps/block, 1 sample/warp
    const int total_threads = batch * 32;
    const int blocks = (total_threads + threads - 1) / threads;

    qsim_kernel<<<blocks, threads>>>(x, weights, post_W, post_b,
                                     readout, bias, out, batch);
}